// round 14
// baseline (speedup 1.0000x reference)
#include <cuda_runtime.h>
#include <cuda_fp16.h>
#include <cstdint>

#define DD    128
#define NNB   32
#define WSTR  132              // w_h stride (u32); fragment-major, re-paired k rows
#define SH    72               // nbH row stride (u32); conflict-free LDS.64/STS.64
#define NGRP  4
#define LRELU_ALPHA 0.2f

// w_h : "k-pair row" R = 8c + r (chunk c of 16 k's, r = 0..7):
//   r < 4 : half2 pair of physical k-rows (16c+4r, 16c+4r+1)
//   r >= 4: pair (16c+4(r-4)+2, +3)
//   within row: pos(e) = (e&7)*16 + (e>>3) (u32), conflict-free LDS.128.
// nbH : row n, entry j = half2( nb[n][2j], nb[n][2j+1] ); double-buffered per group.

__device__ __forceinline__ uint32_t pk_h2(float lo, float hi) {
    __half2 h = __floats2half2_rn(lo, hi);
    return *reinterpret_cast<uint32_t*>(&h);
}

__device__ __forceinline__ void mma_f16(float& c0, float& c1, float& c2, float& c3,
                                        uint32_t a0, uint32_t a1, uint32_t a2, uint32_t a3,
                                        uint32_t b0, uint32_t b1) {
    asm volatile(
        "mma.sync.aligned.m16n8k16.row.col.f32.f16.f16.f32 "
        "{%0,%1,%2,%3}, {%4,%5,%6,%7}, {%8,%9}, {%0,%1,%2,%3};"
        : "+f"(c0), "+f"(c1), "+f"(c2), "+f"(c3)
        : "r"(a0), "r"(a1), "r"(a2), "r"(a3), "r"(b0), "r"(b1));
}

__device__ __forceinline__ void barg(int id) {
    asm volatile("bar.sync %0, 128;" :: "r"(id) : "memory");
}

extern "C" __global__ void __launch_bounds__(512, 1)
gat_h16e(const float* __restrict__ self_v,
         const float* __restrict__ nbv,
         const float* __restrict__ w,
         const float* __restrict__ q,
         float* __restrict__ out,
         int B)
{
    extern __shared__ float sm[];
    uint32_t* w_h  = reinterpret_cast<uint32_t*>(sm);    // 64*132 = 8448 u32
    uint32_t* nbH  = w_h + 64 * WSTR;                    // 4 grp * 2 buf * 32*72 = 18432 u32
    float* scoreP  = sm + 8448 + 18432;                  // 4 grp * 2 buf * 128 = 1024 f
    float* hl_s    = scoreP + NGRP * 2 * 128;            // 4*4*32*2 = 1024 f

    const int t    = threadIdx.x;
    const int lane = t & 31;
    const int ww   = t >> 5;
    const int g    = ww >> 2;
    const int eb   = ww & 3;
    const int gt   = t & 127;
    const int wrow = gt >> 5;
    const int qr   = lane >> 2;
    const int qc   = lane & 3;
    const int bid  = g + 1;
    const int e_lane = 32 * eb + lane;     // this thread's own e index

    uint32_t* nbH_g = nbH + g * 2 * 32 * SH;
    float*    scoreG = scoreP + g * 2 * 128;
    float2*   hl_w   = reinterpret_cast<float2*>(hl_s) + (g * 4 + eb) * NNB;

    // ---- one-time: w -> fp16 re-paired k rows, fragment-major (RN) ----
    {
        #pragma unroll
        for (int i = 0; i < 16; ++i) {                   // 8192 half2 / 512 thr
            const int fi = t + i * 512;
            const int kp = fi >> 7, e = fi & 127;
            const int c  = kp >> 3, r = kp & 7;
            const int d  = (c << 4) + ((r & 3) << 2) + ((r >> 2) << 1);
            w_h[kp * WSTR + (e & 7) * 16 + (e >> 3)] = pk_h2(w[d * DD + e], w[(d + 1) * DD + e]);
        }
    }
    const float qe = q[e_lane];

    const int stride = gridDim.x * NGRP;
    const int p0     = blockIdx.x * NGRP + g;

    // pack 8 float4 (fp32 tile slice) into the given f16 buffer.
    // LDG i of thread gt covers fp32 offsets 512i+4gt -> row 4i+wrow, cols 4*lane..+3
    auto store_tile = [&](const float4* F, int buf) {
        uint32_t* dst = nbH_g + buf * 32 * SH;
        #pragma unroll
        for (int i = 0; i < 8; ++i) {
            uint2 hh;
            hh.x = pk_h2(F[i].x, F[i].y);
            hh.y = pk_h2(F[i].z, F[i].w);
            *reinterpret_cast<uint2*>(dst + (4 * i + wrow) * SH + 2 * lane) = hh;
        }
    };

    // ---- prologue: tile p0 -> buf0; self -> register ----
    float s_cur = 0.f;
    if (p0 < B) {
        float4 F[8];
        const float4* src = reinterpret_cast<const float4*>(nbv + (size_t)p0 * NNB * DD);
        #pragma unroll
        for (int i = 0; i < 8; ++i) F[i] = src[128 * i + gt];
        s_cur = self_v[(size_t)p0 * DD + e_lane];
        store_tile(F, 0);
    }
    __syncthreads();                 // w_h + all groups' buf0 visible

    int it = 0;
    for (int p = p0; p < B; p += stride, ++it) {
        const int cbuf = it & 1;

        // ---- prefetch next batch into registers ----
        const int pn = p + stride;
        const bool have = (pn < B);
        float4 F[8];
        float s_next = 0.f;
        if (have) {
            const float4* src = reinterpret_cast<const float4*>(nbv + (size_t)pn * NNB * DD);
            #pragma unroll
            for (int i = 0; i < 8; ++i) F[i] = src[128 * i + gt];
            s_next = self_v[(size_t)pn * DD + e_lane];
        }

        // ---- warp-private hi/lo (own-lane self/q, then smem broadcast) ----
        {
            const float sq = s_cur * qe;
            const float aq = LRELU_ALPHA * sq;
            hl_w[lane] = (s_cur >= 0.f) ? make_float2(sq, aq) : make_float2(aq, sq);
        }
        __syncwarp();

        // ---- fp16 MMA mainloop: warp tile 32x32, zero packing ----
        float acc[2][4][4];
        #pragma unroll
        for (int T = 0; T < 2; ++T)
            #pragma unroll
            for (int j = 0; j < 4; ++j)
                #pragma unroll
                for (int k = 0; k < 4; ++k) acc[T][j][k] = 0.f;

        const uint32_t* arH = nbH_g + cbuf * 32 * SH + qr * SH + 2 * qc;
        const uint32_t* wp  = w_h + qc * WSTR + qr * 16 + 4 * eb;

        #pragma unroll
        for (int k0 = 0; k0 < DD; k0 += 16) {
            const int kh = k0 >> 1;
            const uint2 A0 = *reinterpret_cast<const uint2*>(arH + kh);            // row qr
            const uint2 A1 = *reinterpret_cast<const uint2*>(arH + 8 * SH + kh);   // qr+8
            const uint2 A2 = *reinterpret_cast<const uint2*>(arH + 16 * SH + kh);  // 16+qr
            const uint2 A3 = *reinterpret_cast<const uint2*>(arH + 24 * SH + kh);  // 24+qr
            const uint4 B0 = *reinterpret_cast<const uint4*>(wp + kh * WSTR);
            const uint4 B1 = *reinterpret_cast<const uint4*>(wp + (kh + 4) * WSTR);

            mma_f16(acc[0][0][0],acc[0][0][1],acc[0][0][2],acc[0][0][3], A0.x,A1.x,A0.y,A1.y, B0.x,B1.x);
            mma_f16(acc[1][0][0],acc[1][0][1],acc[1][0][2],acc[1][0][3], A2.x,A3.x,A2.y,A3.y, B0.x,B1.x);
            mma_f16(acc[0][1][0],acc[0][1][1],acc[0][1][2],acc[0][1][3], A0.x,A1.x,A0.y,A1.y, B0.y,B1.y);
            mma_f16(acc[1][1][0],acc[1][1][1],acc[1][1][2],acc[1][1][3], A2.x,A3.x,A2.y,A3.y, B0.y,B1.y);
            mma_f16(acc[0][2][0],acc[0][2][1],acc[0][2][2],acc[0][2][3], A0.x,A1.x,A0.y,A1.y, B0.z,B1.z);
            mma_f16(acc[1][2][0],acc[1][2][1],acc[1][2][2],acc[1][2][3], A2.x,A3.x,A2.y,A3.y, B0.z,B1.z);
            mma_f16(acc[0][3][0],acc[0][3][1],acc[0][3][2],acc[0][3][3], A0.x,A1.x,A0.y,A1.y, B0.w,B1.w);
            mma_f16(acc[1][3][0],acc[1][3][1],acc[1][3][2],acc[1][3][3], A2.x,A3.x,A2.y,A3.y, B0.w,B1.w);
        }

        // ---- score partials via hi/lo -> scoreG[cbuf] ----
        {
            float pr[4] = {0.f, 0.f, 0.f, 0.f};
            #pragma unroll
            for (int j = 0; j < 4; ++j) {
                const float2 H0 = hl_w[8 * j + 2 * qc];
                const float2 H1 = hl_w[8 * j + 2 * qc + 1];
                #pragma unroll
                for (int T = 0; T < 2; ++T) {
                    float m;
                    m = acc[T][j][0]; pr[2*T]   = fmaf((m >= 0.f) ? H0.x : H0.y, m, pr[2*T]);
                    m = acc[T][j][1]; pr[2*T]   = fmaf((m >= 0.f) ? H1.x : H1.y, m, pr[2*T]);
                    m = acc[T][j][2]; pr[2*T+1] = fmaf((m >= 0.f) ? H0.x : H0.y, m, pr[2*T+1]);
                    m = acc[T][j][3]; pr[2*T+1] = fmaf((m >= 0.f) ? H1.x : H1.y, m, pr[2*T+1]);
                }
            }
            #pragma unroll
            for (int i = 0; i < 4; ++i) {
                pr[i] += __shfl_xor_sync(0xffffffffu, pr[i], 1);
                pr[i] += __shfl_xor_sync(0xffffffffu, pr[i], 2);
            }
            float* sg = scoreG + cbuf * 128;
            if (qc == 0) {
                sg[eb * NNB + qr]      = pr[0];
                sg[eb * NNB + qr + 8]  = pr[1];
                sg[eb * NNB + qr + 16] = pr[2];
                sg[eb * NNB + qr + 24] = pr[3];
            }
        }

        // ---- pack + store NEXT tile into the other buffer (pre-barrier) ----
        if (have) store_tile(F, cbuf ^ 1);

        barg(bid);      // ONE barrier: scoreG[cbuf] + nbH[cbuf^1] visible group-wide

        // ---- softmax, redundantly per warp (bit-identical order) ----
        float al0, al1, al2, al3;
        {
            const float* sg = scoreG + cbuf * 128;
            const float s = sg[lane] + sg[NNB + lane]
                          + sg[2 * NNB + lane] + sg[3 * NNB + lane];
            float mx = s;
            #pragma unroll
            for (int o = 16; o > 0; o >>= 1)
                mx = fmaxf(mx, __shfl_xor_sync(0xffffffffu, mx, o));
            const float ex = __expf(s - mx);
            float sum = ex;
            #pragma unroll
            for (int o = 16; o > 0; o >>= 1)
                sum += __shfl_xor_sync(0xffffffffu, sum, o);
            const float alpha = ex / sum;            // lane holds alpha[lane]
            al0 = __shfl_sync(0xffffffffu, alpha, qr);
            al1 = __shfl_sync(0xffffffffu, alpha, qr + 8);
            al2 = __shfl_sync(0xffffffffu, alpha, qr + 16);
            al3 = __shfl_sync(0xffffffffu, alpha, qr + 24);
        }

        // ---- register epilogue: out[e] = sum_n alpha[n]*msg, direct STG ----
        {
            float val[4][2];
            #pragma unroll
            for (int j = 0; j < 4; ++j)
                #pragma unroll
                for (int u = 0; u < 2; ++u) {
                    float v = al0 * acc[0][j][u];
                    v = fmaf(al1, acc[0][j][2 + u], v);
                    v = fmaf(al2, acc[1][j][u], v);
                    v = fmaf(al3, acc[1][j][2 + u], v);
                    v += __shfl_xor_sync(0xffffffffu, v, 4);
                    v += __shfl_xor_sync(0xffffffffu, v, 8);
                    v += __shfl_xor_sync(0xffffffffu, v, 16);
                    val[j][u] = v;
                }
            if (qr == 0) {
                float* op = out + (size_t)p * DD + 32 * eb + 2 * qc;
                #pragma unroll
                for (int j = 0; j < 4; ++j) {
                    op[8 * j]     = val[j][0];
                    op[8 * j + 1] = val[j][1];
                }
            }
        }

        s_cur = s_next;
    }
}

extern "C" void kernel_launch(void* const* d_in, const int* in_sizes, int n_in,
                              void* d_out, int out_size)
{
    const float* self_v = (const float*)d_in[0];   // [B,128]
    const float* nbv    = (const float*)d_in[1];   // [B,32,128]
    const float* w      = (const float*)d_in[2];   // [128,128]
    const float* q      = (const float*)d_in[3];   // [128,1]
    float*       out    = (float*)d_out;           // [B,128]

    const int B = in_sizes[0] / DD;                // 20000

    int smc = 0;
    cudaDeviceGetAttribute(&smc, cudaDevAttrMultiProcessorCount, 0);
    if (smc <= 0) smc = 148;
    int grid = smc;
    if (grid * NGRP > B) grid = (B + NGRP - 1) / NGRP;

    const size_t smem_bytes =
        (size_t)(64 * WSTR + NGRP * 2 * 32 * SH      // w_h + nbH (u32)
                 + NGRP * 2 * 128                     // scoreP
                 + NGRP * 4 * NNB * 2)                // hl_s
        * 4;                                          // 115,712 B

    cudaFuncSetAttribute(gat_h16e, cudaFuncAttributeMaxDynamicSharedMemorySize,
                         (int)smem_bytes);

    gat_h16e<<<grid, 512, smem_bytes>>>(self_v, nbv, w, q, out, B);
}